// round 15
// baseline (speedup 1.0000x reference)
#include <cuda_runtime.h>
#include <cuda_bf16.h>
#include <stdint.h>
#include <math.h>

#define F 64
#define N_CAP 50176

// ---------------- device scratch ----------------
__device__ float g_asrc[N_CAP * F];
__device__ float g_adst[N_CAP * F];
__device__ float g_v   [N_CAP * F];
__device__ float g_ssum[N_CAP * F];   // sum of exp(alpha) per dst
__device__ float g_num [N_CAP * F];   // sum of exp(alpha)*(v[src]+delta) per dst

// ---------------- mma.sync / ldmatrix helpers ----------------
__device__ __forceinline__ void ldsm4(uint32_t r[4], uint32_t addr) {
    asm volatile("ldmatrix.sync.aligned.m8n8.x4.shared.b16 {%0,%1,%2,%3}, [%4];"
                 : "=r"(r[0]), "=r"(r[1]), "=r"(r[2]), "=r"(r[3]) : "r"(addr));
}
__device__ __forceinline__ void ldsm4t(uint32_t r[4], uint32_t addr) {
    asm volatile("ldmatrix.sync.aligned.m8n8.x4.trans.shared.b16 {%0,%1,%2,%3}, [%4];"
                 : "=r"(r[0]), "=r"(r[1]), "=r"(r[2]), "=r"(r[3]) : "r"(addr));
}
__device__ __forceinline__ void mma16816(float d[4], const uint32_t a[4], uint32_t b0, uint32_t b1) {
    asm volatile("mma.sync.aligned.m16n8k16.row.col.f32.bf16.bf16.f32 "
                 "{%0,%1,%2,%3}, {%4,%5,%6,%7}, {%8,%9}, {%0,%1,%2,%3};"
                 : "+f"(d[0]), "+f"(d[1]), "+f"(d[2]), "+f"(d[3])
                 : "r"(a[0]), "r"(a[1]), "r"(a[2]), "r"(a[3]), "r"(b0), "r"(b1));
}
__device__ __forceinline__ uint32_t smem_u32(const void* p) {
    uint32_t a;
    asm("{ .reg .u64 t; cvta.to.shared.u64 t, %1; cvt.u32.u64 %0, t; }" : "=r"(a) : "l"(p));
    return a;
}
__device__ __forceinline__ void red4(float* p, float a, float b, float c, float d) {
    asm volatile("red.relaxed.gpu.global.add.v4.f32 [%0], {%1, %2, %3, %4};"
                 :: "l"(p), "f"(a), "f"(b), "f"(c), "f"(d) : "memory");
}
__device__ __forceinline__ void pf(const void* p) {
    asm volatile("prefetch.global.L1 [%0];" :: "l"(p));
}
// split fp32 -> bf16 hi (at off) + lo (at off+128)
__device__ __forceinline__ void split1(char* base, uint32_t off, float w) {
    __nv_bfloat16 h = __float2bfloat16(w);
    __nv_bfloat16 l = __float2bfloat16(w - __bfloat162float(h));
    *(__nv_bfloat16*)(base + off) = h;
    *(__nv_bfloat16*)(base + off + 128) = l;
}
__device__ __forceinline__ void split2(char* base, uint32_t off, float a, float b) {
    __nv_bfloat162 h = __float22bfloat162_rn(make_float2(a, b));
    float2 hf = __bfloat1622float2(h);
    __nv_bfloat162 l = __float22bfloat162_rn(make_float2(a - hf.x, b - hf.y));
    *(__nv_bfloat162*)(base + off) = h;
    *(__nv_bfloat162*)(base + off + 128) = l;
}
__device__ __forceinline__ int nperm(int p) {
    return 16 * ((p >> 1) & 3) + 2 * (p >> 3) + (p & 1);
}

// A/B smem rows: [hi 128B][lo 128B][pad 16B] = 272B stride (conflict-free ldmatrix)
// one 64x64x64 GEMM stage (3-pass split: HH + HL + LH)
__device__ __forceinline__ void stage_mma(uint32_t aBase, uint32_t bBase,
                                          uint32_t lrow272, uint32_t lcolb, float acc[8][4])
{
#pragma unroll
    for (int kk = 0; kk < 64; kk += 16) {
        uint32_t aH[4], aL[4];
        uint32_t aaddr = aBase + lrow272 + kk * 2 + lcolb;
        ldsm4(aH, aaddr);
        ldsm4(aL, aaddr + 128);
#pragma unroll
        for (int np = 0; np < 4; np++) {
            uint32_t bH[4], bL[4];
            uint32_t baddr = bBase + kk * 272 + lrow272 + np * 32 + lcolb;
            ldsm4t(bH, baddr);
            ldsm4t(bL, baddr + 128);
            mma16816(acc[2 * np], aH, bH[0], bH[1]);
            mma16816(acc[2 * np], aH, bL[0], bL[1]);
            mma16816(acc[2 * np], aL, bH[0], bH[1]);
            mma16816(acc[2 * np + 1], aH, bH[2], bH[3]);
            mma16816(acc[2 * np + 1], aH, bL[2], bL[3]);
            mma16816(acc[2 * np + 1], aL, bH[2], bH[3]);
        }
    }
}
#define ZACC(acc) { _Pragma("unroll") for (int _i = 0; _i < 8; _i++) \
                    _Pragma("unroll") for (int _j = 0; _j < 4; _j++) (acc)[_i][_j] = 0.f; }

// ============================================================================
// K2: per-edge MLPs on tensor cores; accumulate e and e*(v[src]+delta)
// ============================================================================
#define E_BP1 0
#define E_BP2 256
#define E_BA1 512
#define E_BA2 768
#define E_WP1 1024
#define E_A   2560
#define E_B0  37376
#define E_B1  54784
#define E_B2  72192
#define SMEM_EDGE 89600

__global__ void __launch_bounds__(256, 2) k_edge_tc(
    const float* __restrict__ pos, const int* __restrict__ ei,
    const float* __restrict__ Wp1, const float* __restrict__ bp1,
    const float* __restrict__ Wp2, const float* __restrict__ bp2,
    const float* __restrict__ Wa1, const float* __restrict__ ba1,
    const float* __restrict__ Wa2, const float* __restrict__ ba2,
    int N, int E)
{
    extern __shared__ char smem[];
    const uint32_t sb = smem_u32(smem);
    const int tid  = threadIdx.x;
    const int wid  = tid >> 5;
    const int lane = tid & 31;
    const int wb   = wid * 16;
    const int g    = lane >> 2;
    const int tig  = lane & 3;

    float* sbp1 = (float*)(smem + E_BP1);
    float* sbp2 = (float*)(smem + E_BP2);
    float* sba1 = (float*)(smem + E_BA1);
    float* sba2 = (float*)(smem + E_BA2);
    float* sWp1 = (float*)(smem + E_WP1);

    if (tid < 64) { sbp1[tid] = bp1[tid]; sbp2[tid] = bp2[tid]; sba1[tid] = ba1[tid]; sba2[tid] = ba2[tid]; }
    for (int i = tid; i < 384; i += 256) sWp1[i] = Wp1[i];
    for (int idx = tid; idx < 4096; idx += 256) {
        int k = idx >> 6, p = idx & 63;
        int Lp = nperm(p);
        uint32_t off = (uint32_t)k * 272 + (uint32_t)p * 2;
        split1(smem + E_B0, off, Wp2[k * 64 + Lp]);
        split1(smem + E_B1, off, Wa1[k * 64 + p]);
        split1(smem + E_B2, off, Wa2[k * 64 + Lp]);
    }
    __syncthreads();

    const int TOT = N + E;
    const int NT  = (TOT + 127) >> 7;
    const uint32_t lrow272 = (uint32_t)((lane & 7) + 8 * ((lane >> 3) & 1)) * 272;
    const uint32_t lcolb   = (uint32_t)((lane >> 4) & 1) * 16;
    const uint32_t aBase   = sb + E_A + (uint32_t)wb * 272;
    char* smA = smem + E_A;

    for (int tile = blockIdx.x; tile < NT; tile += gridDim.x) {
        const int tbase = tile << 7;

        // fragment-row bookkeeping + early prefetch of stage-1 gather rows
        const int er1 = wb + g, er2 = er1 + 8;
        const int eid1 = tbase + er1, eid2 = tbase + er2;
        int s1 = 0, d1 = 0, s2 = 0, d2 = 0;
        if (eid1 < TOT) { if (eid1 < E) { s1 = ei[eid1]; d1 = ei[E + eid1]; } else s1 = d1 = eid1 - E; }
        if (eid2 < TOT) { if (eid2 < E) { s2 = ei[eid2]; d2 = ei[E + eid2]; } else s2 = d2 = eid2 - E; }
        pf(g_adst + (size_t)d1 * 64);      pf(g_adst + (size_t)d1 * 64 + 32);
        pf(g_asrc + (size_t)s1 * 64);      pf(g_asrc + (size_t)s1 * 64 + 32);
        pf(g_v    + (size_t)s1 * 64);      pf(g_v    + (size_t)s1 * 64 + 32);
        pf(g_adst + (size_t)d2 * 64);      pf(g_adst + (size_t)d2 * 64 + 32);
        pf(g_asrc + (size_t)s2 * 64);      pf(g_asrc + (size_t)s2 * 64 + 32);
        pf(g_v    + (size_t)s2 * 64);      pf(g_v    + (size_t)s2 * 64 + 32);

        // ---- hidden1 = relu(posdiff @ Wp1 + bp1) -> A ----
        {
            int rh = wb + (lane >> 1);
            int eidh = tbase + rh;
            int sh = 0, dh = 0;
            if (eidh < TOT) {
                if (eidh < E) { sh = ei[eidh]; dh = ei[E + eidh]; }
                else          { sh = dh = eidh - E; }
            }
            float p6[6];
#pragma unroll
            for (int k = 0; k < 6; k++) p6[k] = pos[dh * 6 + k] - pos[sh * 6 + k];
            const int cbase = 32 * (lane & 1);
            const uint32_t rowb = (uint32_t)rh * 272;
#pragma unroll
            for (int cc = 0; cc < 32; cc += 2) {
                int c = cbase + cc;
                float h0 = sbp1[c], h1 = sbp1[c + 1];
#pragma unroll
                for (int k = 0; k < 6; k++) {
                    h0 = fmaf(p6[k], sWp1[k * 64 + c], h0);
                    h1 = fmaf(p6[k], sWp1[k * 64 + c + 1], h1);
                }
                split2(smA, rowb + c * 2, fmaxf(h0, 0.f), fmaxf(h1, 0.f));
            }
        }
        __syncwarp();

        float acc[8][4];
        ZACC(acc);

        // ---- stage 1: delta (n-permuted) ----
        stage_mma(aBase, sb + E_B0, lrow272, lcolb, acc);
        __syncwarp();

        float tvd1[16], tvd2[16];
        {
            const uint32_t rowb1 = (uint32_t)er1 * 272, rowb2 = (uint32_t)er2 * 272;
#pragma unroll
            for (int q = 0; q < 4; q++) {
                const int c = 16 * tig + 4 * q;
                {
                    float4 ad = *(const float4*)(g_adst + (size_t)d1 * 64 + c);
                    float4 as = *(const float4*)(g_asrc + (size_t)s1 * 64 + c);
                    float4 vv = *(const float4*)(g_v    + (size_t)s1 * 64 + c);
                    float e0 = fmaxf(acc[2 * q][0] + sbp2[c + 0], 0.f);
                    float e1 = fmaxf(acc[2 * q][1] + sbp2[c + 1], 0.f);
                    float e2 = fmaxf(acc[2 * q + 1][0] + sbp2[c + 2], 0.f);
                    float e3 = fmaxf(acc[2 * q + 1][1] + sbp2[c + 3], 0.f);
                    split2(smA, rowb1 + c * 2,     ad.x - as.x + e0, ad.y - as.y + e1);
                    split2(smA, rowb1 + c * 2 + 4, ad.z - as.z + e2, ad.w - as.w + e3);
                    tvd1[4 * q + 0] = vv.x + e0; tvd1[4 * q + 1] = vv.y + e1;
                    tvd1[4 * q + 2] = vv.z + e2; tvd1[4 * q + 3] = vv.w + e3;
                }
                {
                    float4 ad = *(const float4*)(g_adst + (size_t)d2 * 64 + c);
                    float4 as = *(const float4*)(g_asrc + (size_t)s2 * 64 + c);
                    float4 vv = *(const float4*)(g_v    + (size_t)s2 * 64 + c);
                    float e0 = fmaxf(acc[2 * q][2] + sbp2[c + 0], 0.f);
                    float e1 = fmaxf(acc[2 * q][3] + sbp2[c + 1], 0.f);
                    float e2 = fmaxf(acc[2 * q + 1][2] + sbp2[c + 2], 0.f);
                    float e3 = fmaxf(acc[2 * q + 1][3] + sbp2[c + 3], 0.f);
                    split2(smA, rowb2 + c * 2,     ad.x - as.x + e0, ad.y - as.y + e1);
                    split2(smA, rowb2 + c * 2 + 4, ad.z - as.z + e2, ad.w - as.w + e3);
                    tvd2[4 * q + 0] = vv.x + e0; tvd2[4 * q + 1] = vv.y + e1;
                    tvd2[4 * q + 2] = vv.z + e2; tvd2[4 * q + 3] = vv.w + e3;
                }
            }
        }
        __syncwarp();

        // ---- stage 2: hidden2 (identity n) ----
        ZACC(acc);
        stage_mma(aBase, sb + E_B1, lrow272, lcolb, acc);
        __syncwarp();
        {
            const uint32_t rowb1 = (uint32_t)er1 * 272, rowb2 = (uint32_t)er2 * 272;
#pragma unroll
            for (int nt = 0; nt < 8; nt++) {
                const int c = 8 * nt + 2 * tig;
                split2(smA, rowb1 + c * 2, fmaxf(acc[nt][0] + sba1[c], 0.f),
                                           fmaxf(acc[nt][1] + sba1[c + 1], 0.f));
                split2(smA, rowb2 + c * 2, fmaxf(acc[nt][2] + sba1[c], 0.f),
                                           fmaxf(acc[nt][3] + sba1[c + 1], 0.f));
            }
        }
        __syncwarp();

        // ---- stage 3: alpha (n-permuted); e=exp; scatter ----
        ZACC(acc);
        stage_mma(aBase, sb + E_B2, lrow272, lcolb, acc);
        __syncwarp();
#pragma unroll
        for (int q = 0; q < 4; q++) {
            const int c = 16 * tig + 4 * q;
            if (eid1 < TOT) {
                float e0 = __expf(fmaxf(acc[2 * q][0] + sba2[c + 0], 0.f));
                float e1 = __expf(fmaxf(acc[2 * q][1] + sba2[c + 1], 0.f));
                float e2 = __expf(fmaxf(acc[2 * q + 1][0] + sba2[c + 2], 0.f));
                float e3 = __expf(fmaxf(acc[2 * q + 1][1] + sba2[c + 3], 0.f));
                red4(g_ssum + (size_t)d1 * 64 + c, e0, e1, e2, e3);
                red4(g_num  + (size_t)d1 * 64 + c, e0 * tvd1[4 * q + 0], e1 * tvd1[4 * q + 1],
                                                   e2 * tvd1[4 * q + 2], e3 * tvd1[4 * q + 3]);
            }
            if (eid2 < TOT) {
                float e0 = __expf(fmaxf(acc[2 * q][2] + sba2[c + 0], 0.f));
                float e1 = __expf(fmaxf(acc[2 * q][3] + sba2[c + 1], 0.f));
                float e2 = __expf(fmaxf(acc[2 * q + 1][2] + sba2[c + 2], 0.f));
                float e3 = __expf(fmaxf(acc[2 * q + 1][3] + sba2[c + 3], 0.f));
                red4(g_ssum + (size_t)d2 * 64 + c, e0, e1, e2, e3);
                red4(g_num  + (size_t)d2 * 64 + c, e0 * tvd2[4 * q + 0], e1 * tvd2[4 * q + 1],
                                                   e2 * tvd2[4 * q + 2], e3 * tvd2[4 * q + 3]);
            }
        }
        __syncwarp();
    }
}

// ============================================================================
// K1 (tensor-core, one tile/CTA): h = relu(x@Win+b); a_src/a_dst/v
// also zero-fills g_ssum / g_num for this tile's rows (replaces memsets)
// ============================================================================
#define P_BIN 0
#define P_A    1024
#define P_BW   35840
#define P_BS   53248
#define P_BD   70656
#define P_BL   88064
#define SMEM_PROJ 105472

__global__ void __launch_bounds__(256, 2) k_proj_tc(
    const float* __restrict__ x,
    const float* __restrict__ Win, const float* __restrict__ bin,
    const float* __restrict__ Wsrc, const float* __restrict__ Wdst,
    const float* __restrict__ Wlin, int N)
{
    extern __shared__ char smem[];
    const uint32_t sb = smem_u32(smem);
    const int tid  = threadIdx.x;
    const int lane = tid & 31;
    const int wid  = tid >> 5;
    const int wb   = wid * 16;
    const int g    = lane >> 2;
    const int tig  = lane & 3;

    float* sbin = (float*)(smem + P_BIN);
    if (tid < 64) sbin[tid] = bin[tid];
    for (int idx = tid; idx < 4096; idx += 256) {
        int k = idx >> 6, p = idx & 63;
        int Lp = nperm(p);
        uint32_t off = (uint32_t)k * 272 + (uint32_t)p * 2;
        split1(smem + P_BW, off, Win[idx]);
        split1(smem + P_BS, off, Wsrc[k * 64 + Lp]);
        split1(smem + P_BD, off, Wdst[k * 64 + Lp]);
        split1(smem + P_BL, off, Wlin[k * 64 + Lp]);
    }
    __syncthreads();

    const uint32_t lrow272 = (uint32_t)((lane & 7) + 8 * ((lane >> 3) & 1)) * 272;
    const uint32_t lcolb   = (uint32_t)((lane >> 4) & 1) * 16;
    const uint32_t aBase   = sb + P_A + (uint32_t)wb * 272;
    char* smA = smem + P_A;

    const int tbase = blockIdx.x << 7;

    // load x rows -> A (bf16 split); zero ssum/num rows (replaces memset)
    {
        int rh = wb + (lane >> 1);
        int row = tbase + rh;
        const int cbase = 32 * (lane & 1);
        const uint32_t rowb = (uint32_t)rh * 272;
        const float4 z = make_float4(0.f, 0.f, 0.f, 0.f);
#pragma unroll
        for (int cc = 0; cc < 32; cc += 4) {
            int c = cbase + cc;
            float4 v = z;
            if (row < N) {
                v = *(const float4*)(x + (size_t)row * 64 + c);
                *(float4*)(g_ssum + (size_t)row * 64 + c) = z;
                *(float4*)(g_num  + (size_t)row * 64 + c) = z;
            }
            split2(smA, rowb + c * 2,     v.x, v.y);
            split2(smA, rowb + c * 2 + 4, v.z, v.w);
        }
    }
    __syncwarp();

    const int er1 = wb + g, er2 = er1 + 8;
    const int row1 = tbase + er1, row2 = tbase + er2;

    float acc[8][4];
    ZACC(acc);
    stage_mma(aBase, sb + P_BW, lrow272, lcolb, acc);
    __syncwarp();
    {
        const uint32_t rowb1 = (uint32_t)er1 * 272, rowb2 = (uint32_t)er2 * 272;
#pragma unroll
        for (int nt = 0; nt < 8; nt++) {
            const int c = 8 * nt + 2 * tig;
            split2(smA, rowb1 + c * 2, fmaxf(acc[nt][0] + sbin[c], 0.f),
                                       fmaxf(acc[nt][1] + sbin[c + 1], 0.f));
            split2(smA, rowb2 + c * 2, fmaxf(acc[nt][2] + sbin[c], 0.f),
                                       fmaxf(acc[nt][3] + sbin[c + 1], 0.f));
        }
    }
    __syncwarp();

    float* outs[3] = { g_asrc, g_adst, g_v };
    const uint32_t boffs[3] = { P_BS, P_BD, P_BL };
#pragma unroll
    for (int t = 0; t < 3; t++) {
        ZACC(acc);
        stage_mma(aBase, sb + boffs[t], lrow272, lcolb, acc);
        __syncwarp();
#pragma unroll
        for (int q = 0; q < 4; q++) {
            const int c = 16 * tig + 4 * q;
            if (row1 < N)
                *(float4*)(outs[t] + (size_t)row1 * 64 + c) =
                    make_float4(acc[2 * q][0], acc[2 * q][1], acc[2 * q + 1][0], acc[2 * q + 1][1]);
            if (row2 < N)
                *(float4*)(outs[t] + (size_t)row2 * 64 + c) =
                    make_float4(acc[2 * q][2], acc[2 * q][3], acc[2 * q + 1][2], acc[2 * q + 1][3]);
        }
        __syncwarp();
    }
}

// ============================================================================
// K3 (tensor-core, one tile/CTA): out = relu((num/ssum) @ Wout + bout) + x
// ============================================================================
#define O_BOUT 0
#define O_A    1024
#define O_BW   35840
#define SMEM_OUT 53248

__global__ void __launch_bounds__(256, 2) k_out_tc(
    const float* __restrict__ x, const float* __restrict__ Wout,
    const float* __restrict__ bout, float* __restrict__ out, int N)
{
    extern __shared__ char smem[];
    const uint32_t sb = smem_u32(smem);
    const int tid  = threadIdx.x;
    const int lane = tid & 31;
    const int wid  = tid >> 5;
    const int wb   = wid * 16;
    const int g    = lane >> 2;
    const int tig  = lane & 3;

    float* sbo = (float*)(smem + O_BOUT);
    if (tid < 64) sbo[tid] = bout[tid];
    for (int idx = tid; idx < 4096; idx += 256) {
        int k = idx >> 6, p = idx & 63;
        uint32_t off = (uint32_t)k * 272 + (uint32_t)p * 2;
        split1(smem + O_BW, off, Wout[k * 64 + nperm(p)]);
    }
    __syncthreads();

    const uint32_t lrow272 = (uint32_t)((lane & 7) + 8 * ((lane >> 3) & 1)) * 272;
    const uint32_t lcolb   = (uint32_t)((lane >> 4) & 1) * 16;
    const uint32_t aBase   = sb + O_A + (uint32_t)wb * 272;
    char* smA = smem + O_A;

    const int tbase = blockIdx.x << 7;
    {
        int rh = wb + (lane >> 1);
        int row = tbase + rh;
        const int cbase = 32 * (lane & 1);
        const uint32_t rowb = (uint32_t)rh * 272;
#pragma unroll
        for (int cc = 0; cc < 32; cc += 4) {
            int c = cbase + cc;
            float4 v = make_float4(0.f, 0.f, 0.f, 0.f);
            if (row < N) {
                float4 n4 = *(const float4*)(g_num  + (size_t)row * 64 + c);
                float4 s4 = *(const float4*)(g_ssum + (size_t)row * 64 + c);
                v = make_float4(n4.x / (s4.x + 1e-16f), n4.y / (s4.y + 1e-16f),
                                n4.z / (s4.z + 1e-16f), n4.w / (s4.w + 1e-16f));
            }
            split2(smA, rowb + c * 2,     v.x, v.y);
            split2(smA, rowb + c * 2 + 4, v.z, v.w);
        }
    }
    __syncwarp();

    const int er1 = wb + g, er2 = er1 + 8;
    const int row1 = tbase + er1, row2 = tbase + er2;

    float acc[8][4];
    ZACC(acc);
    stage_mma(aBase, sb + O_BW, lrow272, lcolb, acc);
    __syncwarp();
#pragma unroll
    for (int q = 0; q < 4; q++) {
        const int c = 16 * tig + 4 * q;
        if (row1 < N) {
            float4 r = *(const float4*)(x + (size_t)row1 * 64 + c);
            *(float4*)(out + (size_t)row1 * 64 + c) =
                make_float4(fmaxf(acc[2 * q][0] + sbo[c + 0], 0.f) + r.x,
                            fmaxf(acc[2 * q][1] + sbo[c + 1], 0.f) + r.y,
                            fmaxf(acc[2 * q + 1][0] + sbo[c + 2], 0.f) + r.z,
                            fmaxf(acc[2 * q + 1][1] + sbo[c + 3], 0.f) + r.w);
        }
        if (row2 < N) {
            float4 r = *(const float4*)(x + (size_t)row2 * 64 + c);
            *(float4*)(out + (size_t)row2 * 64 + c) =
                make_float4(fmaxf(acc[2 * q][2] + sbo[c + 0], 0.f) + r.x,
                            fmaxf(acc[2 * q][3] + sbo[c + 1], 0.f) + r.y,
                            fmaxf(acc[2 * q + 1][2] + sbo[c + 2], 0.f) + r.z,
                            fmaxf(acc[2 * q + 1][3] + sbo[c + 3], 0.f) + r.w);
        }
    }
}

// ---------------- host ----------------
extern "C" void kernel_launch(void* const* d_in, const int* in_sizes, int n_in,
                              void* d_out, int out_size)
{
    const float* x    = (const float*)d_in[0];
    const float* pos  = (const float*)d_in[1];
    const int*   ei   = (const int*)  d_in[2];
    const float* Win  = (const float*)d_in[3];
    const float* bin  = (const float*)d_in[4];
    const float* Wout = (const float*)d_in[5];
    const float* bout = (const float*)d_in[6];
    const float* Wlin = (const float*)d_in[7];
    const float* Wsrc = (const float*)d_in[8];
    const float* Wdst = (const float*)d_in[9];
    const float* Wp1  = (const float*)d_in[10];
    const float* bp1  = (const float*)d_in[11];
    const float* Wp2  = (const float*)d_in[12];
    const float* bp2  = (const float*)d_in[13];
    const float* Wa1  = (const float*)d_in[14];
    const float* ba1  = (const float*)d_in[15];
    const float* Wa2  = (const float*)d_in[16];
    const float* ba2  = (const float*)d_in[17];

    const int N = in_sizes[0] / 64;
    const int E = in_sizes[2] / 2;

    cudaFuncSetAttribute(k_proj_tc, cudaFuncAttributeMaxDynamicSharedMemorySize, SMEM_PROJ);
    cudaFuncSetAttribute(k_edge_tc, cudaFuncAttributeMaxDynamicSharedMemorySize, SMEM_EDGE);
    cudaFuncSetAttribute(k_out_tc,  cudaFuncAttributeMaxDynamicSharedMemorySize, SMEM_OUT);

    const int ntile = (N + 127) / 128;
    k_proj_tc<<<ntile, 256, SMEM_PROJ>>>(x, Win, bin, Wsrc, Wdst, Wlin, N);
    k_edge_tc<<<296, 256, SMEM_EDGE>>>(pos, ei, Wp1, bp1, Wp2, bp2, Wa1, ba1, Wa2, ba2, N, E);
    k_out_tc<<<ntile, 256, SMEM_OUT>>>(x, Wout, bout, (float*)d_out, N);
}

// round 16
// speedup vs baseline: 1.5750x; 1.5750x over previous
#include <cuda_runtime.h>
#include <cuda_bf16.h>
#include <stdint.h>
#include <math.h>

#define F 64
#define N_CAP 50176

// ---------------- device scratch ----------------
__device__ float g_asrc[N_CAP * F];
__device__ float g_adst[N_CAP * F];
__device__ float g_v   [N_CAP * F];
__device__ float g_ssum[N_CAP * F];   // sum of exp(alpha) per dst
__device__ float g_num [N_CAP * F];   // sum of exp(alpha)*(v[src]+delta) per dst

// ---------------- mma.sync / ldmatrix helpers ----------------
__device__ __forceinline__ void ldsm4(uint32_t r[4], uint32_t addr) {
    asm volatile("ldmatrix.sync.aligned.m8n8.x4.shared.b16 {%0,%1,%2,%3}, [%4];"
                 : "=r"(r[0]), "=r"(r[1]), "=r"(r[2]), "=r"(r[3]) : "r"(addr));
}
__device__ __forceinline__ void ldsm4t(uint32_t r[4], uint32_t addr) {
    asm volatile("ldmatrix.sync.aligned.m8n8.x4.trans.shared.b16 {%0,%1,%2,%3}, [%4];"
                 : "=r"(r[0]), "=r"(r[1]), "=r"(r[2]), "=r"(r[3]) : "r"(addr));
}
__device__ __forceinline__ void mma16816(float d[4], const uint32_t a[4], uint32_t b0, uint32_t b1) {
    asm volatile("mma.sync.aligned.m16n8k16.row.col.f32.bf16.bf16.f32 "
                 "{%0,%1,%2,%3}, {%4,%5,%6,%7}, {%8,%9}, {%0,%1,%2,%3};"
                 : "+f"(d[0]), "+f"(d[1]), "+f"(d[2]), "+f"(d[3])
                 : "r"(a[0]), "r"(a[1]), "r"(a[2]), "r"(a[3]), "r"(b0), "r"(b1));
}
__device__ __forceinline__ uint32_t smem_u32(const void* p) {
    uint32_t a;
    asm("{ .reg .u64 t; cvta.to.shared.u64 t, %1; cvt.u32.u64 %0, t; }" : "=r"(a) : "l"(p));
    return a;
}
__device__ __forceinline__ void red4(float* p, float a, float b, float c, float d) {
    asm volatile("red.relaxed.gpu.global.add.v4.f32 [%0], {%1, %2, %3, %4};"
                 :: "l"(p), "f"(a), "f"(b), "f"(c), "f"(d) : "memory");
}
// split fp32 -> bf16 hi (at off) + lo (at off+128)
__device__ __forceinline__ void split1(char* base, uint32_t off, float w) {
    __nv_bfloat16 h = __float2bfloat16(w);
    __nv_bfloat16 l = __float2bfloat16(w - __bfloat162float(h));
    *(__nv_bfloat16*)(base + off) = h;
    *(__nv_bfloat16*)(base + off + 128) = l;
}
__device__ __forceinline__ void split2(char* base, uint32_t off, float a, float b) {
    __nv_bfloat162 h = __float22bfloat162_rn(make_float2(a, b));
    float2 hf = __bfloat1622float2(h);
    __nv_bfloat162 l = __float22bfloat162_rn(make_float2(a - hf.x, b - hf.y));
    *(__nv_bfloat162*)(base + off) = h;
    *(__nv_bfloat162*)(base + off + 128) = l;
}
__device__ __forceinline__ int nperm(int p) {
    return 16 * ((p >> 1) & 3) + 2 * (p >> 3) + (p & 1);
}

// A/B smem rows: [hi 128B][lo 128B][pad 16B] = 272B stride (conflict-free ldmatrix)
// one 64x64x64 GEMM stage (3-pass split: HH + HL + LH)
__device__ __forceinline__ void stage_mma(uint32_t aBase, uint32_t bBase,
                                          uint32_t lrow272, uint32_t lcolb, float acc[8][4])
{
#pragma unroll
    for (int kk = 0; kk < 64; kk += 16) {
        uint32_t aH[4], aL[4];
        uint32_t aaddr = aBase + lrow272 + kk * 2 + lcolb;
        ldsm4(aH, aaddr);
        ldsm4(aL, aaddr + 128);
#pragma unroll
        for (int np = 0; np < 4; np++) {
            uint32_t bH[4], bL[4];
            uint32_t baddr = bBase + kk * 272 + lrow272 + np * 32 + lcolb;
            ldsm4t(bH, baddr);
            ldsm4t(bL, baddr + 128);
            mma16816(acc[2 * np], aH, bH[0], bH[1]);
            mma16816(acc[2 * np], aH, bL[0], bL[1]);
            mma16816(acc[2 * np], aL, bH[0], bH[1]);
            mma16816(acc[2 * np + 1], aH, bH[2], bH[3]);
            mma16816(acc[2 * np + 1], aH, bL[2], bL[3]);
            mma16816(acc[2 * np + 1], aL, bH[2], bH[3]);
        }
    }
}
#define ZACC(acc) { _Pragma("unroll") for (int _i = 0; _i < 8; _i++) \
                    _Pragma("unroll") for (int _j = 0; _j < 4; _j++) (acc)[_i][_j] = 0.f; }

// ============================================================================
// K2: per-edge MLPs on tensor cores; accumulate e and e*(v[src]+delta)
// ============================================================================
#define E_BP1 0
#define E_BP2 256
#define E_BA1 512
#define E_BA2 768
#define E_WP1 1024
#define E_A   2560
#define E_B0  37376
#define E_B1  54784
#define E_B2  72192
#define SMEM_EDGE 89600

__global__ void __launch_bounds__(256, 2) k_edge_tc(
    const float* __restrict__ pos, const int* __restrict__ ei,
    const float* __restrict__ Wp1, const float* __restrict__ bp1,
    const float* __restrict__ Wp2, const float* __restrict__ bp2,
    const float* __restrict__ Wa1, const float* __restrict__ ba1,
    const float* __restrict__ Wa2, const float* __restrict__ ba2,
    int N, int E)
{
    extern __shared__ char smem[];
    const uint32_t sb = smem_u32(smem);
    const int tid  = threadIdx.x;
    const int wid  = tid >> 5;
    const int lane = tid & 31;
    const int wb   = wid * 16;
    const int g    = lane >> 2;
    const int tig  = lane & 3;

    float* sbp1 = (float*)(smem + E_BP1);
    float* sbp2 = (float*)(smem + E_BP2);
    float* sba1 = (float*)(smem + E_BA1);
    float* sba2 = (float*)(smem + E_BA2);
    float* sWp1 = (float*)(smem + E_WP1);

    if (tid < 64) { sbp1[tid] = bp1[tid]; sbp2[tid] = bp2[tid]; sba1[tid] = ba1[tid]; sba2[tid] = ba2[tid]; }
    for (int i = tid; i < 384; i += 256) sWp1[i] = Wp1[i];
    for (int idx = tid; idx < 4096; idx += 256) {
        int k = idx >> 6, p = idx & 63;
        int Lp = nperm(p);
        uint32_t off = (uint32_t)k * 272 + (uint32_t)p * 2;
        split1(smem + E_B0, off, Wp2[k * 64 + Lp]);
        split1(smem + E_B1, off, Wa1[k * 64 + p]);
        split1(smem + E_B2, off, Wa2[k * 64 + Lp]);
    }
    __syncthreads();

    const int TOT = N + E;
    const int NT  = (TOT + 127) >> 7;
    const uint32_t lrow272 = (uint32_t)((lane & 7) + 8 * ((lane >> 3) & 1)) * 272;
    const uint32_t lcolb   = (uint32_t)((lane >> 4) & 1) * 16;
    const uint32_t aBase   = sb + E_A + (uint32_t)wb * 272;
    char* smA = smem + E_A;

    for (int tile = blockIdx.x; tile < NT; tile += gridDim.x) {
        const int tbase = tile << 7;

        // ---- hidden1 = relu(posdiff @ Wp1 + bp1) -> A (warp-local rows) ----
        {
            int rh = wb + (lane >> 1);
            int eidh = tbase + rh;
            int sh = 0, dh = 0;
            if (eidh < TOT) {
                if (eidh < E) { sh = ei[eidh]; dh = ei[E + eidh]; }
                else          { sh = dh = eidh - E; }
            }
            float p6[6];
#pragma unroll
            for (int k = 0; k < 6; k++) p6[k] = pos[dh * 6 + k] - pos[sh * 6 + k];
            const int cbase = 32 * (lane & 1);
            const uint32_t rowb = (uint32_t)rh * 272;
#pragma unroll
            for (int cc = 0; cc < 32; cc += 2) {
                int c = cbase + cc;
                float h0 = sbp1[c], h1 = sbp1[c + 1];
#pragma unroll
                for (int k = 0; k < 6; k++) {
                    h0 = fmaf(p6[k], sWp1[k * 64 + c], h0);
                    h1 = fmaf(p6[k], sWp1[k * 64 + c + 1], h1);
                }
                split2(smA, rowb + c * 2, fmaxf(h0, 0.f), fmaxf(h1, 0.f));
            }
        }
        __syncwarp();

        // fragment-row bookkeeping
        const int er1 = wb + g, er2 = er1 + 8;
        const int eid1 = tbase + er1, eid2 = tbase + er2;
        int s1 = 0, d1 = 0, s2 = 0, d2 = 0;
        if (eid1 < TOT) { if (eid1 < E) { s1 = ei[eid1]; d1 = ei[E + eid1]; } else s1 = d1 = eid1 - E; }
        if (eid2 < TOT) { if (eid2 < E) { s2 = ei[eid2]; d2 = ei[E + eid2]; } else s2 = d2 = eid2 - E; }

        float acc[8][4];
        ZACC(acc);

        // ---- stage 1: delta = relu(hidden1 @ Wp2 + bp2)  (n-permuted) ----
        stage_mma(aBase, sb + E_B0, lrow272, lcolb, acc);
        __syncwarp();

        float tvd1[16], tvd2[16];
        {
            const uint32_t rowb1 = (uint32_t)er1 * 272, rowb2 = (uint32_t)er2 * 272;
#pragma unroll
            for (int q = 0; q < 4; q++) {
                const int c = 16 * tig + 4 * q;
                {
                    float4 ad = *(const float4*)(g_adst + (size_t)d1 * 64 + c);
                    float4 as = *(const float4*)(g_asrc + (size_t)s1 * 64 + c);
                    float4 vv = *(const float4*)(g_v    + (size_t)s1 * 64 + c);
                    float e0 = fmaxf(acc[2 * q][0] + sbp2[c + 0], 0.f);
                    float e1 = fmaxf(acc[2 * q][1] + sbp2[c + 1], 0.f);
                    float e2 = fmaxf(acc[2 * q + 1][0] + sbp2[c + 2], 0.f);
                    float e3 = fmaxf(acc[2 * q + 1][1] + sbp2[c + 3], 0.f);
                    split2(smA, rowb1 + c * 2,     ad.x - as.x + e0, ad.y - as.y + e1);
                    split2(smA, rowb1 + c * 2 + 4, ad.z - as.z + e2, ad.w - as.w + e3);
                    tvd1[4 * q + 0] = vv.x + e0; tvd1[4 * q + 1] = vv.y + e1;
                    tvd1[4 * q + 2] = vv.z + e2; tvd1[4 * q + 3] = vv.w + e3;
                }
                {
                    float4 ad = *(const float4*)(g_adst + (size_t)d2 * 64 + c);
                    float4 as = *(const float4*)(g_asrc + (size_t)s2 * 64 + c);
                    float4 vv = *(const float4*)(g_v    + (size_t)s2 * 64 + c);
                    float e0 = fmaxf(acc[2 * q][2] + sbp2[c + 0], 0.f);
                    float e1 = fmaxf(acc[2 * q][3] + sbp2[c + 1], 0.f);
                    float e2 = fmaxf(acc[2 * q + 1][2] + sbp2[c + 2], 0.f);
                    float e3 = fmaxf(acc[2 * q + 1][3] + sbp2[c + 3], 0.f);
                    split2(smA, rowb2 + c * 2,     ad.x - as.x + e0, ad.y - as.y + e1);
                    split2(smA, rowb2 + c * 2 + 4, ad.z - as.z + e2, ad.w - as.w + e3);
                    tvd2[4 * q + 0] = vv.x + e0; tvd2[4 * q + 1] = vv.y + e1;
                    tvd2[4 * q + 2] = vv.z + e2; tvd2[4 * q + 3] = vv.w + e3;
                }
            }
        }
        __syncwarp();

        // ---- stage 2: hidden2 = relu(y @ Wa1 + ba1)  (identity n) ----
        ZACC(acc);
        stage_mma(aBase, sb + E_B1, lrow272, lcolb, acc);
        __syncwarp();
        {
            const uint32_t rowb1 = (uint32_t)er1 * 272, rowb2 = (uint32_t)er2 * 272;
#pragma unroll
            for (int nt = 0; nt < 8; nt++) {
                const int c = 8 * nt + 2 * tig;
                split2(smA, rowb1 + c * 2, fmaxf(acc[nt][0] + sba1[c], 0.f),
                                           fmaxf(acc[nt][1] + sba1[c + 1], 0.f));
                split2(smA, rowb2 + c * 2, fmaxf(acc[nt][2] + sba1[c], 0.f),
                                           fmaxf(acc[nt][3] + sba1[c + 1], 0.f));
            }
        }
        __syncwarp();

        // ---- stage 3: alpha (n-permuted); e=exp; scatter ----
        ZACC(acc);
        stage_mma(aBase, sb + E_B2, lrow272, lcolb, acc);
        __syncwarp();
#pragma unroll
        for (int q = 0; q < 4; q++) {
            const int c = 16 * tig + 4 * q;
            if (eid1 < TOT) {
                float e0 = __expf(fmaxf(acc[2 * q][0] + sba2[c + 0], 0.f));
                float e1 = __expf(fmaxf(acc[2 * q][1] + sba2[c + 1], 0.f));
                float e2 = __expf(fmaxf(acc[2 * q + 1][0] + sba2[c + 2], 0.f));
                float e3 = __expf(fmaxf(acc[2 * q + 1][1] + sba2[c + 3], 0.f));
                red4(g_ssum + (size_t)d1 * 64 + c, e0, e1, e2, e3);
                red4(g_num  + (size_t)d1 * 64 + c, e0 * tvd1[4 * q + 0], e1 * tvd1[4 * q + 1],
                                                   e2 * tvd1[4 * q + 2], e3 * tvd1[4 * q + 3]);
            }
            if (eid2 < TOT) {
                float e0 = __expf(fmaxf(acc[2 * q][2] + sba2[c + 0], 0.f));
                float e1 = __expf(fmaxf(acc[2 * q][3] + sba2[c + 1], 0.f));
                float e2 = __expf(fmaxf(acc[2 * q + 1][2] + sba2[c + 2], 0.f));
                float e3 = __expf(fmaxf(acc[2 * q + 1][3] + sba2[c + 3], 0.f));
                red4(g_ssum + (size_t)d2 * 64 + c, e0, e1, e2, e3);
                red4(g_num  + (size_t)d2 * 64 + c, e0 * tvd2[4 * q + 0], e1 * tvd2[4 * q + 1],
                                                   e2 * tvd2[4 * q + 2], e3 * tvd2[4 * q + 3]);
            }
        }
        __syncwarp();
    }
}

// ============================================================================
// K1 (tensor-core): h = relu(x@Win+b); a_src/a_dst/v = h @ {Wsrc,Wdst,Wlin}
// ============================================================================
#define P_BIN 0
#define P_A    1024
#define P_BW   35840   // Win (identity n)
#define P_BS   53248   // Wsrc (n-perm)
#define P_BD   70656   // Wdst (n-perm)
#define P_BL   88064   // Wlin (n-perm)
#define SMEM_PROJ 105472

__global__ void __launch_bounds__(256, 2) k_proj_tc(
    const float* __restrict__ x,
    const float* __restrict__ Win, const float* __restrict__ bin,
    const float* __restrict__ Wsrc, const float* __restrict__ Wdst,
    const float* __restrict__ Wlin, int N)
{
    extern __shared__ char smem[];
    const uint32_t sb = smem_u32(smem);
    const int tid  = threadIdx.x;
    const int wid  = tid >> 5;
    const int lane = tid & 31;
    const int wb   = wid * 16;
    const int g    = lane >> 2;
    const int tig  = lane & 3;

    float* sbin = (float*)(smem + P_BIN);
    if (tid < 64) sbin[tid] = bin[tid];
    for (int idx = tid; idx < 4096; idx += 256) {
        int k = idx >> 6, p = idx & 63;
        int Lp = nperm(p);
        uint32_t off = (uint32_t)k * 272 + (uint32_t)p * 2;
        split1(smem + P_BW, off, Win[idx]);
        split1(smem + P_BS, off, Wsrc[k * 64 + Lp]);
        split1(smem + P_BD, off, Wdst[k * 64 + Lp]);
        split1(smem + P_BL, off, Wlin[k * 64 + Lp]);
    }
    __syncthreads();

    const uint32_t lrow272 = (uint32_t)((lane & 7) + 8 * ((lane >> 3) & 1)) * 272;
    const uint32_t lcolb   = (uint32_t)((lane >> 4) & 1) * 16;
    const uint32_t aBase   = sb + P_A + (uint32_t)wb * 272;
    char* smA = smem + P_A;

    const int tbase = blockIdx.x << 7;

    // load x rows -> A (bf16 split)
    {
        int rh = wb + (lane >> 1);
        int row = tbase + rh;
        const int cbase = 32 * (lane & 1);
        const uint32_t rowb = (uint32_t)rh * 272;
#pragma unroll
        for (int cc = 0; cc < 32; cc += 4) {
            int c = cbase + cc;
            float4 v = (row < N) ? *(const float4*)(x + (size_t)row * 64 + c)
                                 : make_float4(0.f, 0.f, 0.f, 0.f);
            split2(smA, rowb + c * 2,     v.x, v.y);
            split2(smA, rowb + c * 2 + 4, v.z, v.w);
        }
    }
    __syncwarp();

    const int er1 = wb + g, er2 = er1 + 8;
    const int row1 = tbase + er1, row2 = tbase + er2;

    float acc[8][4];
    // h = relu(x@Win + bin) -> A (identity n epilogue)
    ZACC(acc);
    stage_mma(aBase, sb + P_BW, lrow272, lcolb, acc);
    __syncwarp();
    {
        const uint32_t rowb1 = (uint32_t)er1 * 272, rowb2 = (uint32_t)er2 * 272;
#pragma unroll
        for (int nt = 0; nt < 8; nt++) {
            const int c = 8 * nt + 2 * tig;
            split2(smA, rowb1 + c * 2, fmaxf(acc[nt][0] + sbin[c], 0.f),
                                       fmaxf(acc[nt][1] + sbin[c + 1], 0.f));
            split2(smA, rowb2 + c * 2, fmaxf(acc[nt][2] + sbin[c], 0.f),
                                       fmaxf(acc[nt][3] + sbin[c + 1], 0.f));
        }
    }
    __syncwarp();

    float* outs[3] = { g_asrc, g_adst, g_v };
    const uint32_t boffs[3] = { P_BS, P_BD, P_BL };
#pragma unroll
    for (int t = 0; t < 3; t++) {
        ZACC(acc);
        stage_mma(aBase, sb + boffs[t], lrow272, lcolb, acc);
        __syncwarp();
#pragma unroll
        for (int q = 0; q < 4; q++) {
            const int c = 16 * tig + 4 * q;
            if (row1 < N)
                *(float4*)(outs[t] + (size_t)row1 * 64 + c) =
                    make_float4(acc[2 * q][0], acc[2 * q][1], acc[2 * q + 1][0], acc[2 * q + 1][1]);
            if (row2 < N)
                *(float4*)(outs[t] + (size_t)row2 * 64 + c) =
                    make_float4(acc[2 * q][2], acc[2 * q][3], acc[2 * q + 1][2], acc[2 * q + 1][3]);
        }
        __syncwarp();
    }
}

// ============================================================================
// K3 (tensor-core): out = relu((num/ssum) @ Wout + bout) + x
// ============================================================================
#define O_BOUT 0
#define O_A    1024
#define O_BW   35840  // Wout (n-perm)
#define SMEM_OUT 53248

__global__ void __launch_bounds__(256, 2) k_out_tc(
    const float* __restrict__ x, const float* __restrict__ Wout,
    const float* __restrict__ bout, float* __restrict__ out, int N)
{
    extern __shared__ char smem[];
    const uint32_t sb = smem_u32(smem);
    const int tid  = threadIdx.x;
    const int wid  = tid >> 5;
    const int lane = tid & 31;
    const int wb   = wid * 16;
    const int g    = lane >> 2;
    const int tig  = lane & 3;

    float* sbo = (float*)(smem + O_BOUT);
    if (tid < 64) sbo[tid] = bout[tid];
    for (int idx = tid; idx < 4096; idx += 256) {
        int k = idx >> 6, p = idx & 63;
        uint32_t off = (uint32_t)k * 272 + (uint32_t)p * 2;
        split1(smem + O_BW, off, Wout[k * 64 + nperm(p)]);
    }
    __syncthreads();

    const uint32_t lrow272 = (uint32_t)((lane & 7) + 8 * ((lane >> 3) & 1)) * 272;
    const uint32_t lcolb   = (uint32_t)((lane >> 4) & 1) * 16;
    const uint32_t aBase   = sb + O_A + (uint32_t)wb * 272;
    char* smA = smem + O_A;

    const int tbase = blockIdx.x << 7;
    {
        int rh = wb + (lane >> 1);
        int row = tbase + rh;
        const int cbase = 32 * (lane & 1);
        const uint32_t rowb = (uint32_t)rh * 272;
#pragma unroll
        for (int cc = 0; cc < 32; cc += 4) {
            int c = cbase + cc;
            float4 v = make_float4(0.f, 0.f, 0.f, 0.f);
            if (row < N) {
                float4 n4 = *(const float4*)(g_num  + (size_t)row * 64 + c);
                float4 s4 = *(const float4*)(g_ssum + (size_t)row * 64 + c);
                v = make_float4(n4.x / (s4.x + 1e-16f), n4.y / (s4.y + 1e-16f),
                                n4.z / (s4.z + 1e-16f), n4.w / (s4.w + 1e-16f));
            }
            split2(smA, rowb + c * 2,     v.x, v.y);
            split2(smA, rowb + c * 2 + 4, v.z, v.w);
        }
    }
    __syncwarp();

    const int er1 = wb + g, er2 = er1 + 8;
    const int row1 = tbase + er1, row2 = tbase + er2;

    float acc[8][4];
    ZACC(acc);
    stage_mma(aBase, sb + O_BW, lrow272, lcolb, acc);
    __syncwarp();
#pragma unroll
    for (int q = 0; q < 4; q++) {
        const int c = 16 * tig + 4 * q;
        if (row1 < N) {
            float4 r = *(const float4*)(x + (size_t)row1 * 64 + c);
            *(float4*)(out + (size_t)row1 * 64 + c) =
                make_float4(fmaxf(acc[2 * q][0] + sbo[c + 0], 0.f) + r.x,
                            fmaxf(acc[2 * q][1] + sbo[c + 1], 0.f) + r.y,
                            fmaxf(acc[2 * q + 1][0] + sbo[c + 2], 0.f) + r.z,
                            fmaxf(acc[2 * q + 1][1] + sbo[c + 3], 0.f) + r.w);
        }
        if (row2 < N) {
            float4 r = *(const float4*)(x + (size_t)row2 * 64 + c);
            *(float4*)(out + (size_t)row2 * 64 + c) =
                make_float4(fmaxf(acc[2 * q][2] + sbo[c + 0], 0.f) + r.x,
                            fmaxf(acc[2 * q][3] + sbo[c + 1], 0.f) + r.y,
                            fmaxf(acc[2 * q + 1][2] + sbo[c + 2], 0.f) + r.z,
                            fmaxf(acc[2 * q + 1][3] + sbo[c + 3], 0.f) + r.w);
        }
    }
}

// ---------------- host ----------------
extern "C" void kernel_launch(void* const* d_in, const int* in_sizes, int n_in,
                              void* d_out, int out_size)
{
    const float* x    = (const float*)d_in[0];
    const float* pos  = (const float*)d_in[1];
    const int*   ei   = (const int*)  d_in[2];
    const float* Win  = (const float*)d_in[3];
    const float* bin  = (const float*)d_in[4];
    const float* Wout = (const float*)d_in[5];
    const float* bout = (const float*)d_in[6];
    const float* Wlin = (const float*)d_in[7];
    const float* Wsrc = (const float*)d_in[8];
    const float* Wdst = (const float*)d_in[9];
    const float* Wp1  = (const float*)d_in[10];
    const float* bp1  = (const float*)d_in[11];
    const float* Wp2  = (const float*)d_in[12];
    const float* bp2  = (const float*)d_in[13];
    const float* Wa1  = (const float*)d_in[14];
    const float* ba1  = (const float*)d_in[15];
    const float* Wa2  = (const float*)d_in[16];
    const float* ba2  = (const float*)d_in[17];

    const int N = in_sizes[0] / 64;
    const int E = in_sizes[2] / 2;

    void *p_ssum, *p_num;
    cudaGetSymbolAddress(&p_ssum, g_ssum);
    cudaGetSymbolAddress(&p_num,  g_num);
    cudaMemsetAsync(p_ssum, 0, (size_t)N * 64 * sizeof(float), 0);
    cudaMemsetAsync(p_num,  0, (size_t)N * 64 * sizeof(float), 0);

    cudaFuncSetAttribute(k_proj_tc, cudaFuncAttributeMaxDynamicSharedMemorySize, SMEM_PROJ);
    cudaFuncSetAttribute(k_edge_tc, cudaFuncAttributeMaxDynamicSharedMemorySize, SMEM_EDGE);
    cudaFuncSetAttribute(k_out_tc,  cudaFuncAttributeMaxDynamicSharedMemorySize, SMEM_OUT);

    const int ntile = (N + 127) / 128;
    k_proj_tc<<<ntile, 256, SMEM_PROJ>>>(x, Win, bin, Wsrc, Wdst, Wlin, N);
    k_edge_tc<<<296, 256, SMEM_EDGE>>>(pos, ei, Wp1, bp1, Wp2, bp2, Wa1, ba1, Wa2, ba2, N, E);
    k_out_tc<<<ntile, 256, SMEM_OUT>>>(x, Wout, bout, (float*)d_out, N);
}

// round 17
// speedup vs baseline: 1.5823x; 1.0046x over previous
#include <cuda_runtime.h>
#include <cuda_bf16.h>
#include <stdint.h>
#include <math.h>

#define F 64
#define N_CAP 50176

// ---------------- device scratch ----------------
__device__ float g_asrc[N_CAP * F];
__device__ float g_adst[N_CAP * F];
__device__ float g_v   [N_CAP * F];
__device__ float g_ssum[N_CAP * F];   // sum of exp(alpha) per dst
__device__ float g_num [N_CAP * F];   // sum of exp(alpha)*(v[src]+delta) per dst

// ---------------- mma.sync / ldmatrix helpers ----------------
__device__ __forceinline__ void ldsm4(uint32_t r[4], uint32_t addr) {
    asm volatile("ldmatrix.sync.aligned.m8n8.x4.shared.b16 {%0,%1,%2,%3}, [%4];"
                 : "=r"(r[0]), "=r"(r[1]), "=r"(r[2]), "=r"(r[3]) : "r"(addr));
}
__device__ __forceinline__ void ldsm4t(uint32_t r[4], uint32_t addr) {
    asm volatile("ldmatrix.sync.aligned.m8n8.x4.trans.shared.b16 {%0,%1,%2,%3}, [%4];"
                 : "=r"(r[0]), "=r"(r[1]), "=r"(r[2]), "=r"(r[3]) : "r"(addr));
}
__device__ __forceinline__ void mma16816(float d[4], const uint32_t a[4], uint32_t b0, uint32_t b1) {
    asm volatile("mma.sync.aligned.m16n8k16.row.col.f32.bf16.bf16.f32 "
                 "{%0,%1,%2,%3}, {%4,%5,%6,%7}, {%8,%9}, {%0,%1,%2,%3};"
                 : "+f"(d[0]), "+f"(d[1]), "+f"(d[2]), "+f"(d[3])
                 : "r"(a[0]), "r"(a[1]), "r"(a[2]), "r"(a[3]), "r"(b0), "r"(b1));
}
__device__ __forceinline__ uint32_t smem_u32(const void* p) {
    uint32_t a;
    asm("{ .reg .u64 t; cvta.to.shared.u64 t, %1; cvt.u32.u64 %0, t; }" : "=r"(a) : "l"(p));
    return a;
}
__device__ __forceinline__ void red4(float* p, float a, float b, float c, float d) {
    asm volatile("red.relaxed.gpu.global.add.v4.f32 [%0], {%1, %2, %3, %4};"
                 :: "l"(p), "f"(a), "f"(b), "f"(c), "f"(d) : "memory");
}
// split fp32 -> bf16 hi (at off) + lo (at off+128)
__device__ __forceinline__ void split1(char* base, uint32_t off, float w) {
    __nv_bfloat16 h = __float2bfloat16(w);
    __nv_bfloat16 l = __float2bfloat16(w - __bfloat162float(h));
    *(__nv_bfloat16*)(base + off) = h;
    *(__nv_bfloat16*)(base + off + 128) = l;
}
__device__ __forceinline__ void split2(char* base, uint32_t off, float a, float b) {
    __nv_bfloat162 h = __float22bfloat162_rn(make_float2(a, b));
    float2 hf = __bfloat1622float2(h);
    __nv_bfloat162 l = __float22bfloat162_rn(make_float2(a - hf.x, b - hf.y));
    *(__nv_bfloat162*)(base + off) = h;
    *(__nv_bfloat162*)(base + off + 128) = l;
}
__device__ __forceinline__ int nperm(int p) {
    return 16 * ((p >> 1) & 3) + 2 * (p >> 3) + (p & 1);
}

// A/B smem rows: [hi 128B][lo 128B][pad 16B] = 272B stride (conflict-free ldmatrix)
// one 64x64x64 GEMM stage (3-pass split: HH + HL + LH)
__device__ __forceinline__ void stage_mma(uint32_t aBase, uint32_t bBase,
                                          uint32_t lrow272, uint32_t lcolb, float acc[8][4])
{
#pragma unroll
    for (int kk = 0; kk < 64; kk += 16) {
        uint32_t aH[4], aL[4];
        uint32_t aaddr = aBase + lrow272 + kk * 2 + lcolb;
        ldsm4(aH, aaddr);
        ldsm4(aL, aaddr + 128);
#pragma unroll
        for (int np = 0; np < 4; np++) {
            uint32_t bH[4], bL[4];
            uint32_t baddr = bBase + kk * 272 + lrow272 + np * 32 + lcolb;
            ldsm4t(bH, baddr);
            ldsm4t(bL, baddr + 128);
            mma16816(acc[2 * np], aH, bH[0], bH[1]);
            mma16816(acc[2 * np], aH, bL[0], bL[1]);
            mma16816(acc[2 * np], aL, bH[0], bH[1]);
            mma16816(acc[2 * np + 1], aH, bH[2], bH[3]);
            mma16816(acc[2 * np + 1], aH, bL[2], bL[3]);
            mma16816(acc[2 * np + 1], aL, bH[2], bH[3]);
        }
    }
}
#define ZACC(acc) { _Pragma("unroll") for (int _i = 0; _i < 8; _i++) \
                    _Pragma("unroll") for (int _j = 0; _j < 4; _j++) (acc)[_i][_j] = 0.f; }

// ============================================================================
// K2: per-edge MLPs on tensor cores; accumulate e and e*(v[src]+delta)
// ============================================================================
#define E_BP1 0
#define E_BP2 256
#define E_BA1 512
#define E_BA2 768
#define E_WP1 1024
#define E_A   2560
#define E_B0  37376
#define E_B1  54784
#define E_B2  72192
#define SMEM_EDGE 89600

__global__ void __launch_bounds__(256, 2) k_edge_tc(
    const float* __restrict__ pos, const int* __restrict__ ei,
    const float* __restrict__ Wp1, const float* __restrict__ bp1,
    const float* __restrict__ Wp2, const float* __restrict__ bp2,
    const float* __restrict__ Wa1, const float* __restrict__ ba1,
    const float* __restrict__ Wa2, const float* __restrict__ ba2,
    int N, int E)
{
    extern __shared__ char smem[];
    const uint32_t sb = smem_u32(smem);
    const int tid  = threadIdx.x;
    const int wid  = tid >> 5;
    const int lane = tid & 31;
    const int wb   = wid * 16;
    const int g    = lane >> 2;
    const int tig  = lane & 3;

    float* sbp1 = (float*)(smem + E_BP1);
    float* sbp2 = (float*)(smem + E_BP2);
    float* sba1 = (float*)(smem + E_BA1);
    float* sba2 = (float*)(smem + E_BA2);
    float* sWp1 = (float*)(smem + E_WP1);

    if (tid < 64) { sbp1[tid] = bp1[tid]; sbp2[tid] = bp2[tid]; sba1[tid] = ba1[tid]; sba2[tid] = ba2[tid]; }
    for (int i = tid; i < 384; i += 256) sWp1[i] = Wp1[i];
    for (int idx = tid; idx < 4096; idx += 256) {
        int k = idx >> 6, p = idx & 63;
        int Lp = nperm(p);
        uint32_t off = (uint32_t)k * 272 + (uint32_t)p * 2;
        split1(smem + E_B0, off, Wp2[k * 64 + Lp]);
        split1(smem + E_B1, off, Wa1[k * 64 + p]);
        split1(smem + E_B2, off, Wa2[k * 64 + Lp]);
    }
    __syncthreads();

    const int TOT = N + E;
    const int NT  = (TOT + 127) >> 7;
    const uint32_t lrow272 = (uint32_t)((lane & 7) + 8 * ((lane >> 3) & 1)) * 272;
    const uint32_t lcolb   = (uint32_t)((lane >> 4) & 1) * 16;
    const uint32_t aBase   = sb + E_A + (uint32_t)wb * 272;
    char* smA = smem + E_A;

    for (int tile = blockIdx.x; tile < NT; tile += gridDim.x) {
        const int tbase = tile << 7;

        // ---- hidden1 = relu(posdiff @ Wp1 + bp1) -> A (warp-local rows) ----
        {
            int rh = wb + (lane >> 1);
            int eidh = tbase + rh;
            int sh = 0, dh = 0;
            if (eidh < TOT) {
                if (eidh < E) { sh = ei[eidh]; dh = ei[E + eidh]; }
                else          { sh = dh = eidh - E; }
            }
            float p6[6];
#pragma unroll
            for (int k = 0; k < 6; k++) p6[k] = pos[dh * 6 + k] - pos[sh * 6 + k];
            const int cbase = 32 * (lane & 1);
            const uint32_t rowb = (uint32_t)rh * 272;
#pragma unroll
            for (int cc = 0; cc < 32; cc += 2) {
                int c = cbase + cc;
                float h0 = sbp1[c], h1 = sbp1[c + 1];
#pragma unroll
                for (int k = 0; k < 6; k++) {
                    h0 = fmaf(p6[k], sWp1[k * 64 + c], h0);
                    h1 = fmaf(p6[k], sWp1[k * 64 + c + 1], h1);
                }
                split2(smA, rowb + c * 2, fmaxf(h0, 0.f), fmaxf(h1, 0.f));
            }
        }
        __syncwarp();

        // fragment-row bookkeeping
        const int er1 = wb + g, er2 = er1 + 8;
        const int eid1 = tbase + er1, eid2 = tbase + er2;
        int s1 = 0, d1 = 0, s2 = 0, d2 = 0;
        if (eid1 < TOT) { if (eid1 < E) { s1 = ei[eid1]; d1 = ei[E + eid1]; } else s1 = d1 = eid1 - E; }
        if (eid2 < TOT) { if (eid2 < E) { s2 = ei[eid2]; d2 = ei[E + eid2]; } else s2 = d2 = eid2 - E; }

        float acc[8][4];
        ZACC(acc);

        // ---- stage 1: delta = relu(hidden1 @ Wp2 + bp2)  (n-permuted) ----
        stage_mma(aBase, sb + E_B0, lrow272, lcolb, acc);
        __syncwarp();

        float tvd1[16], tvd2[16];
        {
            const uint32_t rowb1 = (uint32_t)er1 * 272, rowb2 = (uint32_t)er2 * 272;
#pragma unroll
            for (int q = 0; q < 4; q++) {
                const int c = 16 * tig + 4 * q;
                {
                    float4 ad = *(const float4*)(g_adst + (size_t)d1 * 64 + c);
                    float4 as = *(const float4*)(g_asrc + (size_t)s1 * 64 + c);
                    float4 vv = *(const float4*)(g_v    + (size_t)s1 * 64 + c);
                    float e0 = fmaxf(acc[2 * q][0] + sbp2[c + 0], 0.f);
                    float e1 = fmaxf(acc[2 * q][1] + sbp2[c + 1], 0.f);
                    float e2 = fmaxf(acc[2 * q + 1][0] + sbp2[c + 2], 0.f);
                    float e3 = fmaxf(acc[2 * q + 1][1] + sbp2[c + 3], 0.f);
                    split2(smA, rowb1 + c * 2,     ad.x - as.x + e0, ad.y - as.y + e1);
                    split2(smA, rowb1 + c * 2 + 4, ad.z - as.z + e2, ad.w - as.w + e3);
                    tvd1[4 * q + 0] = vv.x + e0; tvd1[4 * q + 1] = vv.y + e1;
                    tvd1[4 * q + 2] = vv.z + e2; tvd1[4 * q + 3] = vv.w + e3;
                }
                {
                    float4 ad = *(const float4*)(g_adst + (size_t)d2 * 64 + c);
                    float4 as = *(const float4*)(g_asrc + (size_t)s2 * 64 + c);
                    float4 vv = *(const float4*)(g_v    + (size_t)s2 * 64 + c);
                    float e0 = fmaxf(acc[2 * q][2] + sbp2[c + 0], 0.f);
                    float e1 = fmaxf(acc[2 * q][3] + sbp2[c + 1], 0.f);
                    float e2 = fmaxf(acc[2 * q + 1][2] + sbp2[c + 2], 0.f);
                    float e3 = fmaxf(acc[2 * q + 1][3] + sbp2[c + 3], 0.f);
                    split2(smA, rowb2 + c * 2,     ad.x - as.x + e0, ad.y - as.y + e1);
                    split2(smA, rowb2 + c * 2 + 4, ad.z - as.z + e2, ad.w - as.w + e3);
                    tvd2[4 * q + 0] = vv.x + e0; tvd2[4 * q + 1] = vv.y + e1;
                    tvd2[4 * q + 2] = vv.z + e2; tvd2[4 * q + 3] = vv.w + e3;
                }
            }
        }
        __syncwarp();

        // ---- stage 2: hidden2 = relu(y @ Wa1 + ba1)  (identity n) ----
        ZACC(acc);
        stage_mma(aBase, sb + E_B1, lrow272, lcolb, acc);
        __syncwarp();
        {
            const uint32_t rowb1 = (uint32_t)er1 * 272, rowb2 = (uint32_t)er2 * 272;
#pragma unroll
            for (int nt = 0; nt < 8; nt++) {
                const int c = 8 * nt + 2 * tig;
                split2(smA, rowb1 + c * 2, fmaxf(acc[nt][0] + sba1[c], 0.f),
                                           fmaxf(acc[nt][1] + sba1[c + 1], 0.f));
                split2(smA, rowb2 + c * 2, fmaxf(acc[nt][2] + sba1[c], 0.f),
                                           fmaxf(acc[nt][3] + sba1[c + 1], 0.f));
            }
        }
        __syncwarp();

        // ---- stage 3: alpha (n-permuted); e=exp; scatter ----
        ZACC(acc);
        stage_mma(aBase, sb + E_B2, lrow272, lcolb, acc);
        __syncwarp();
#pragma unroll
        for (int q = 0; q < 4; q++) {
            const int c = 16 * tig + 4 * q;
            if (eid1 < TOT) {
                float e0 = __expf(fmaxf(acc[2 * q][0] + sba2[c + 0], 0.f));
                float e1 = __expf(fmaxf(acc[2 * q][1] + sba2[c + 1], 0.f));
                float e2 = __expf(fmaxf(acc[2 * q + 1][0] + sba2[c + 2], 0.f));
                float e3 = __expf(fmaxf(acc[2 * q + 1][1] + sba2[c + 3], 0.f));
                red4(g_ssum + (size_t)d1 * 64 + c, e0, e1, e2, e3);
                red4(g_num  + (size_t)d1 * 64 + c, e0 * tvd1[4 * q + 0], e1 * tvd1[4 * q + 1],
                                                   e2 * tvd1[4 * q + 2], e3 * tvd1[4 * q + 3]);
            }
            if (eid2 < TOT) {
                float e0 = __expf(fmaxf(acc[2 * q][2] + sba2[c + 0], 0.f));
                float e1 = __expf(fmaxf(acc[2 * q][3] + sba2[c + 1], 0.f));
                float e2 = __expf(fmaxf(acc[2 * q + 1][2] + sba2[c + 2], 0.f));
                float e3 = __expf(fmaxf(acc[2 * q + 1][3] + sba2[c + 3], 0.f));
                red4(g_ssum + (size_t)d2 * 64 + c, e0, e1, e2, e3);
                red4(g_num  + (size_t)d2 * 64 + c, e0 * tvd2[4 * q + 0], e1 * tvd2[4 * q + 1],
                                                   e2 * tvd2[4 * q + 2], e3 * tvd2[4 * q + 3]);
            }
        }
        __syncwarp();
    }
}

// ============================================================================
// K1 (tensor-core): h = relu(x@Win+b); a_src/a_dst/v = h @ {Wsrc,Wdst,Wlin}
// ============================================================================
#define P_BIN 0
#define P_A    1024
#define P_BW   35840   // Win (identity n)
#define P_BS   53248   // Wsrc (n-perm)
#define P_BD   70656   // Wdst (n-perm)
#define P_BL   88064   // Wlin (n-perm)
#define SMEM_PROJ 105472

__global__ void __launch_bounds__(256, 2) k_proj_tc(
    const float* __restrict__ x,
    const float* __restrict__ Win, const float* __restrict__ bin,
    const float* __restrict__ Wsrc, const float* __restrict__ Wdst,
    const float* __restrict__ Wlin, int N)
{
    extern __shared__ char smem[];
    const uint32_t sb = smem_u32(smem);
    const int tid  = threadIdx.x;
    const int wid  = tid >> 5;
    const int lane = tid & 31;
    const int wb   = wid * 16;
    const int g    = lane >> 2;
    const int tig  = lane & 3;

    float* sbin = (float*)(smem + P_BIN);
    if (tid < 64) sbin[tid] = bin[tid];
    for (int idx = tid; idx < 4096; idx += 256) {
        int k = idx >> 6, p = idx & 63;
        int Lp = nperm(p);
        uint32_t off = (uint32_t)k * 272 + (uint32_t)p * 2;
        split1(smem + P_BW, off, Win[idx]);
        split1(smem + P_BS, off, Wsrc[k * 64 + Lp]);
        split1(smem + P_BD, off, Wdst[k * 64 + Lp]);
        split1(smem + P_BL, off, Wlin[k * 64 + Lp]);
    }
    __syncthreads();

    const uint32_t lrow272 = (uint32_t)((lane & 7) + 8 * ((lane >> 3) & 1)) * 272;
    const uint32_t lcolb   = (uint32_t)((lane >> 4) & 1) * 16;
    const uint32_t aBase   = sb + P_A + (uint32_t)wb * 272;
    char* smA = smem + P_A;

    const int tbase = blockIdx.x << 7;

    // load x rows -> A (bf16 split)
    {
        int rh = wb + (lane >> 1);
        int row = tbase + rh;
        const int cbase = 32 * (lane & 1);
        const uint32_t rowb = (uint32_t)rh * 272;
#pragma unroll
        for (int cc = 0; cc < 32; cc += 4) {
            int c = cbase + cc;
            float4 v = (row < N) ? *(const float4*)(x + (size_t)row * 64 + c)
                                 : make_float4(0.f, 0.f, 0.f, 0.f);
            split2(smA, rowb + c * 2,     v.x, v.y);
            split2(smA, rowb + c * 2 + 4, v.z, v.w);
        }
    }
    __syncwarp();

    const int er1 = wb + g, er2 = er1 + 8;
    const int row1 = tbase + er1, row2 = tbase + er2;

    float acc[8][4];
    // h = relu(x@Win + bin) -> A (identity n epilogue)
    ZACC(acc);
    stage_mma(aBase, sb + P_BW, lrow272, lcolb, acc);
    __syncwarp();
    {
        const uint32_t rowb1 = (uint32_t)er1 * 272, rowb2 = (uint32_t)er2 * 272;
#pragma unroll
        for (int nt = 0; nt < 8; nt++) {
            const int c = 8 * nt + 2 * tig;
            split2(smA, rowb1 + c * 2, fmaxf(acc[nt][0] + sbin[c], 0.f),
                                       fmaxf(acc[nt][1] + sbin[c + 1], 0.f));
            split2(smA, rowb2 + c * 2, fmaxf(acc[nt][2] + sbin[c], 0.f),
                                       fmaxf(acc[nt][3] + sbin[c + 1], 0.f));
        }
    }
    __syncwarp();

    float* outs[3] = { g_asrc, g_adst, g_v };
    const uint32_t boffs[3] = { P_BS, P_BD, P_BL };
#pragma unroll
    for (int t = 0; t < 3; t++) {
        ZACC(acc);
        stage_mma(aBase, sb + boffs[t], lrow272, lcolb, acc);
        __syncwarp();
#pragma unroll
        for (int q = 0; q < 4; q++) {
            const int c = 16 * tig + 4 * q;
            if (row1 < N)
                *(float4*)(outs[t] + (size_t)row1 * 64 + c) =
                    make_float4(acc[2 * q][0], acc[2 * q][1], acc[2 * q + 1][0], acc[2 * q + 1][1]);
            if (row2 < N)
                *(float4*)(outs[t] + (size_t)row2 * 64 + c) =
                    make_float4(acc[2 * q][2], acc[2 * q][3], acc[2 * q + 1][2], acc[2 * q + 1][3]);
        }
        __syncwarp();
    }
}

// ============================================================================
// K3 (tensor-core): out = relu((num/ssum) @ Wout + bout) + x
// ============================================================================
#define O_BOUT 0
#define O_A    1024
#define O_BW   35840  // Wout (n-perm)
#define SMEM_OUT 53248

__global__ void __launch_bounds__(256, 2) k_out_tc(
    const float* __restrict__ x, const float* __restrict__ Wout,
    const float* __restrict__ bout, float* __restrict__ out, int N)
{
    extern __shared__ char smem[];
    const uint32_t sb = smem_u32(smem);
    const int tid  = threadIdx.x;
    const int wid  = tid >> 5;
    const int lane = tid & 31;
    const int wb   = wid * 16;
    const int g    = lane >> 2;
    const int tig  = lane & 3;

    float* sbo = (float*)(smem + O_BOUT);
    if (tid < 64) sbo[tid] = bout[tid];
    for (int idx = tid; idx < 4096; idx += 256) {
        int k = idx >> 6, p = idx & 63;
        uint32_t off = (uint32_t)k * 272 + (uint32_t)p * 2;
        split1(smem + O_BW, off, Wout[k * 64 + nperm(p)]);
    }
    __syncthreads();

    const uint32_t lrow272 = (uint32_t)((lane & 7) + 8 * ((lane >> 3) & 1)) * 272;
    const uint32_t lcolb   = (uint32_t)((lane >> 4) & 1) * 16;
    const uint32_t aBase   = sb + O_A + (uint32_t)wb * 272;
    char* smA = smem + O_A;

    const int tbase = blockIdx.x << 7;
    {
        int rh = wb + (lane >> 1);
        int row = tbase + rh;
        const int cbase = 32 * (lane & 1);
        const uint32_t rowb = (uint32_t)rh * 272;
#pragma unroll
        for (int cc = 0; cc < 32; cc += 4) {
            int c = cbase + cc;
            float4 v = make_float4(0.f, 0.f, 0.f, 0.f);
            if (row < N) {
                float4 n4 = *(const float4*)(g_num  + (size_t)row * 64 + c);
                float4 s4 = *(const float4*)(g_ssum + (size_t)row * 64 + c);
                v = make_float4(n4.x / (s4.x + 1e-16f), n4.y / (s4.y + 1e-16f),
                                n4.z / (s4.z + 1e-16f), n4.w / (s4.w + 1e-16f));
            }
            split2(smA, rowb + c * 2,     v.x, v.y);
            split2(smA, rowb + c * 2 + 4, v.z, v.w);
        }
    }
    __syncwarp();

    const int er1 = wb + g, er2 = er1 + 8;
    const int row1 = tbase + er1, row2 = tbase + er2;

    float acc[8][4];
    ZACC(acc);
    stage_mma(aBase, sb + O_BW, lrow272, lcolb, acc);
    __syncwarp();
#pragma unroll
    for (int q = 0; q < 4; q++) {
        const int c = 16 * tig + 4 * q;
        if (row1 < N) {
            float4 r = *(const float4*)(x + (size_t)row1 * 64 + c);
            *(float4*)(out + (size_t)row1 * 64 + c) =
                make_float4(fmaxf(acc[2 * q][0] + sbo[c + 0], 0.f) + r.x,
                            fmaxf(acc[2 * q][1] + sbo[c + 1], 0.f) + r.y,
                            fmaxf(acc[2 * q + 1][0] + sbo[c + 2], 0.f) + r.z,
                            fmaxf(acc[2 * q + 1][1] + sbo[c + 3], 0.f) + r.w);
        }
        if (row2 < N) {
            float4 r = *(const float4*)(x + (size_t)row2 * 64 + c);
            *(float4*)(out + (size_t)row2 * 64 + c) =
                make_float4(fmaxf(acc[2 * q][2] + sbo[c + 0], 0.f) + r.x,
                            fmaxf(acc[2 * q][3] + sbo[c + 1], 0.f) + r.y,
                            fmaxf(acc[2 * q + 1][2] + sbo[c + 2], 0.f) + r.z,
                            fmaxf(acc[2 * q + 1][3] + sbo[c + 3], 0.f) + r.w);
        }
    }
}

// ---------------- host ----------------
extern "C" void kernel_launch(void* const* d_in, const int* in_sizes, int n_in,
                              void* d_out, int out_size)
{
    const float* x    = (const float*)d_in[0];
    const float* pos  = (const float*)d_in[1];
    const int*   ei   = (const int*)  d_in[2];
    const float* Win  = (const float*)d_in[3];
    const float* bin  = (const float*)d_in[4];
    const float* Wout = (const float*)d_in[5];
    const float* bout = (const float*)d_in[6];
    const float* Wlin = (const float*)d_in[7];
    const float* Wsrc = (const float*)d_in[8];
    const float* Wdst = (const float*)d_in[9];
    const float* Wp1  = (const float*)d_in[10];
    const float* bp1  = (const float*)d_in[11];
    const float* Wp2  = (const float*)d_in[12];
    const float* bp2  = (const float*)d_in[13];
    const float* Wa1  = (const float*)d_in[14];
    const float* ba1  = (const float*)d_in[15];
    const float* Wa2  = (const float*)d_in[16];
    const float* ba2  = (const float*)d_in[17];

    const int N = in_sizes[0] / 64;
    const int E = in_sizes[2] / 2;

    void *p_ssum, *p_num;
    cudaGetSymbolAddress(&p_ssum, g_ssum);
    cudaGetSymbolAddress(&p_num,  g_num);
    cudaMemsetAsync(p_ssum, 0, (size_t)N * 64 * sizeof(float), 0);
    cudaMemsetAsync(p_num,  0, (size_t)N * 64 * sizeof(float), 0);

    cudaFuncSetAttribute(k_proj_tc, cudaFuncAttributeMaxDynamicSharedMemorySize, SMEM_PROJ);
    cudaFuncSetAttribute(k_edge_tc, cudaFuncAttributeMaxDynamicSharedMemorySize, SMEM_EDGE);
    cudaFuncSetAttribute(k_out_tc,  cudaFuncAttributeMaxDynamicSharedMemorySize, SMEM_OUT);

    const int ntile = (N + 127) / 128;
    k_proj_tc<<<ntile, 256, SMEM_PROJ>>>(x, Win, bin, Wsrc, Wdst, Wlin, N);
    k_edge_tc<<<296, 256, SMEM_EDGE>>>(pos, ei, Wp1, bp1, Wp2, bp2, Wa1, ba1, Wa2, ba2, N, E);
    k_out_tc<<<ntile, 256, SMEM_OUT>>>(x, Wout, bout, (float*)d_out, N);
}